// round 4
// baseline (speedup 1.0000x reference)
#include <cuda_runtime.h>

#define NN 50000
#define NE 100000
#define NODE_IN 64
#define EDGE_IN 16
#define H 32
#define EH 128
#define NTN 343
#define NTE 21
#define STEPS 6
#define NBLK ((NE + 255) / 256)   // 391

// ---------------- device scratch (no allocations allowed) ----------------
__device__ float d_h[NN * H];           // current hidden
__device__ float d_agg[NN * H];         // aggregated messages
__device__ float d_msg[NE * H];         // per-edge messages (type-sorted order)
__device__ float d_Wtab[NTE * H * H];   // per-type edge weight matrices
__device__ int d_ssrc[NE];              // type-sorted src
__device__ int d_sdst[NE];              // type-sorted dst (only for glist build)
__device__ int d_stype[NE];             // type per sorted edge
__device__ int d_blkcnt[NBLK * NTE];    // blockwise type histogram
__device__ int d_dcnt[NN];              // dst histogram
__device__ int d_rowptr[NN + 1];        // CSR row pointers (by dst)
__device__ int d_dcur[NN];              // working cursors
__device__ int d_glist[NE];             // positions (in sorted order) grouped by dst

// ---------------- helpers ----------------
__device__ __forceinline__ unsigned long long pk(float a, float b) {
    unsigned long long r;
    asm("mov.b64 %0, {%1, %2};" : "=l"(r) : "f"(a), "f"(b));
    return r;
}
__device__ __forceinline__ float2 upk(unsigned long long v) {
    float2 f;
    asm("mov.b64 {%0, %1}, %2;" : "=f"(f.x), "=f"(f.y) : "l"(v));
    return f;
}
__device__ __forceinline__ void ffma2(unsigned long long& acc,
                                      unsigned long long a,
                                      unsigned long long b) {
    asm("fma.rn.f32x2 %0, %1, %2, %0;" : "+l"(acc) : "l"(a), "l"(b));
}
__device__ __forceinline__ float sigm(float x) {
    return 1.0f / (1.0f + __expf(-x));
}
__device__ __forceinline__ float tanh_fast(float x) {
    float e = __expf(2.0f * x);
    return 1.0f - 2.0f / (e + 1.0f);
}

// ---------------- launch 0: blockwise type histogram + zero d_dcnt ----------
__global__ void k_count(const int* __restrict__ eid) {
    __shared__ int hc[NTE];
    if (threadIdx.x < NTE) hc[threadIdx.x] = 0;
    __syncthreads();
    int e = blockIdx.x * blockDim.x + threadIdx.x;
    if (e < NE) atomicAdd(&hc[eid[e]], 1);
    if (e < NN) d_dcnt[e] = 0;   // 100k threads >= 50k entries
    __syncthreads();
    if (threadIdx.x < NTE) d_blkcnt[blockIdx.x * NTE + threadIdx.x] = hc[threadIdx.x];
}

// ---------------- launch 1: type-sort scatter (fused global prefix) ---------
__global__ void k_scatter(const int* __restrict__ eid,
                          const int* __restrict__ src,
                          const int* __restrict__ dst) {
    __shared__ int hc[NTE];
    __shared__ int hbase[NTE];
    __shared__ int htot[NTE];
    int b = blockIdx.x;
    if (threadIdx.x < NTE) hc[threadIdx.x] = 0;
    __syncthreads();
    int e = b * blockDim.x + threadIdx.x;
    int t = 0, loc = 0, dd = 0;
    bool valid = (e < NE);
    if (valid) {
        t = eid[e];
        dd = dst[e];
        loc = atomicAdd(&hc[t], 1);
    }
    __syncthreads();
    if (threadIdx.x < NTE) {
        int tt = threadIdx.x, before = 0, total = 0;
        for (int bb = 0; bb < NBLK; bb++) {
            int c = d_blkcnt[bb * NTE + tt];
            total += c;
            if (bb < b) before += c;
        }
        hbase[tt] = before;
        htot[tt] = total;
    }
    __syncthreads();
    if (threadIdx.x == 0) {
        int run = 0;
        for (int tt = 0; tt < NTE; tt++) {
            hbase[tt] += run;
            run += htot[tt];
        }
    }
    __syncthreads();
    if (valid) {
        int p = hbase[t] + loc;
        d_ssrc[p] = src[e];
        d_sdst[p] = dd;
        d_stype[p] = t;
        atomicAdd(&d_dcnt[dd], 1);
    }
}

// ---------------- launch 2: block 0 = dst prefix scan; blocks 1..21 = wtab --
__global__ void __launch_bounds__(1024) k_scan_wtab(
    const float* __restrict__ edge_emb,
    const float* __restrict__ eW1,
    const float* __restrict__ eb1,
    const float* __restrict__ eW2,
    const float* __restrict__ eb2) {
    int tid = threadIdx.x;
    if (blockIdx.x == 0) {
        // exclusive prefix over d_dcnt[NN]
        __shared__ int part[1024];
        const int CH = (NN + 1023) / 1024;  // 49
        int lo = tid * CH, hi = min(NN, lo + CH);
        int s = 0;
        for (int j = lo; j < hi; j++) s += d_dcnt[j];
        part[tid] = s;
        __syncthreads();
        for (int off = 1; off < 1024; off <<= 1) {
            int v = (tid >= off) ? part[tid - off] : 0;
            __syncthreads();
            part[tid] += v;
            __syncthreads();
        }
        int run = tid ? part[tid - 1] : 0;
        for (int j = lo; j < hi; j++) {
            d_rowptr[j] = run;
            d_dcur[j] = run;
            run += d_dcnt[j];
        }
        if (tid == 0) d_rowptr[NN] = NE;
    } else {
        // one block per edge type
        int t = blockIdx.x - 1;
        __shared__ float sh[EH];
        if (tid < EH) {
            float a = eb1[tid];
#pragma unroll
            for (int i = 0; i < EDGE_IN; i++)
                a = fmaf(edge_emb[t * EDGE_IN + i], eW1[i * EH + tid], a);
            sh[tid] = fmaxf(a, 0.0f);
        }
        __syncthreads();
        float acc = eb2[tid];
#pragma unroll 8
        for (int i = 0; i < EH; i++)
            acc = fmaf(sh[i], eW2[i * (H * H) + tid], acc);
        d_Wtab[t * (H * H) + tid] = acc;
    }
}

// ---------------- launch 3: build dst-grouped position list ----------------
__global__ void k_scatter2() {
    int p = blockIdx.x * blockDim.x + threadIdx.x;
    if (p < NE) {
        int d = d_sdst[p];
        int slot = atomicAdd(&d_dcur[d], 1);
        d_glist[slot] = p;
    }
}

// ---------------- launch 4: init h (inline projection) ---------------------
__global__ void k_init(const int* __restrict__ node_ids,
                       const float* __restrict__ node_emb,
                       const float* __restrict__ proj_W,
                       const float* __restrict__ proj_b) {
    int idx = blockIdx.x * blockDim.x + threadIdx.x;
    if (idx >= NN * H) return;
    int n = idx >> 5, o = idx & 31;
    int nid = node_ids[n];
    float acc = proj_b[o];
#pragma unroll 8
    for (int i = 0; i < NODE_IN; i++)
        acc = fmaf(node_emb[nid * NODE_IN + i], proj_W[i * H + o], acc);
    d_h[idx] = fmaxf(acc, 0.0f);
}

// ---------------- launch 5: message kernel (NO atomics) --------------------
// Warp owns 32 type-sorted edges: stage h[src] rows in smem, W in registers
// (packed f32x2, reloaded only at rare type boundaries), plain coalesced STG
// of the per-edge message into d_msg.
#define MSG_TPB 256
#define MSG_WPB (MSG_TPB / 32)
#define MSG_NWARPS ((NE + 31) / 32)
#define MSG_BLOCKS ((MSG_NWARPS + MSG_WPB - 1) / MSG_WPB)

__global__ void __launch_bounds__(MSG_TPB) k_message() {
    __shared__ __align__(16) float hs[MSG_WPB][32][32];
    int wid = threadIdx.x >> 5;
    int lane = threadIdx.x & 31;
    int gw = blockIdx.x * MSG_WPB + wid;
    int base = gw * 32;
    if (base >= NE) return;
    int nb = min(32, NE - base);
    const unsigned FULL = 0xffffffffu;

    int s = 0, t = 0;
    if (lane < nb) {
        int e = base + lane;
        s = __ldg(&d_ssrc[e]);
        t = __ldg(&d_stype[e]);
    }

    // stage h rows (independent coalesced 128B loads)
#pragma unroll 4
    for (int j = 0; j < nb; j++) {
        int sj = __shfl_sync(FULL, s, j);
        hs[wid][j][lane] = d_h[sj * H + lane];
    }

    int cur_t = __shfl_sync(FULL, t, 0);
    unsigned long long w2[H / 2];
    {
        const float* Wt = d_Wtab + cur_t * (H * H);
#pragma unroll
        for (int q = 0; q < H / 2; q++)
            w2[q] = pk(Wt[(2 * q) * H + lane], Wt[(2 * q + 1) * H + lane]);
    }
    __syncwarp();

#pragma unroll 2
    for (int j = 0; j < nb; j++) {
        int tj = __shfl_sync(FULL, t, j);
        if (tj != cur_t) {
            cur_t = tj;
            const float* Wt = d_Wtab + cur_t * (H * H);
#pragma unroll
            for (int q = 0; q < H / 2; q++)
                w2[q] = pk(Wt[(2 * q) * H + lane], Wt[(2 * q + 1) * H + lane]);
        }
        const ulonglong2* hp = (const ulonglong2*)hs[wid][j];
        unsigned long long acc = 0;
#pragma unroll
        for (int p = 0; p < 8; p++) {
            ulonglong2 hh = hp[p];
            ffma2(acc, hh.x, w2[2 * p]);
            ffma2(acc, hh.y, w2[2 * p + 1]);
        }
        float2 f = upk(acc);
        d_msg[(base + j) * H + lane] = f.x + f.y;
    }
}

// ---------------- aggregate: warp per node, CSR gather-sum ------------------
#define AGG_TPB 256
#define AGG_WPB (AGG_TPB / 32)
#define AGG_BLOCKS ((NN + AGG_WPB - 1) / AGG_WPB)

__global__ void __launch_bounds__(AGG_TPB) k_agg() {
    int wid = threadIdx.x >> 5;
    int lane = threadIdx.x & 31;
    int n = blockIdx.x * AGG_WPB + wid;
    if (n >= NN) return;
    const unsigned FULL = 0xffffffffu;
    int start = __ldg(&d_rowptr[n]);
    int end = __ldg(&d_rowptr[n + 1]);
    float acc = 0.0f;
    for (int k0 = start; k0 < end; k0 += 32) {
        int kk = k0 + lane;
        int g = (kk < end) ? __ldg(&d_glist[kk]) : 0;
        int cnt = min(32, end - k0);
        for (int j = 0; j < cnt; j++) {
            int pos = __shfl_sync(FULL, g, j);
            acc += d_msg[pos * H + lane];
        }
    }
    d_agg[n * H + lane] = acc;
}

// ---------------- GRU kernel ----------------
__global__ void k_gru(const float* __restrict__ gWih,
                      const float* __restrict__ gWhh,
                      const float* __restrict__ gbih,
                      const float* __restrict__ gbhh,
                      const float* __restrict__ cb,
                      float* __restrict__ outp) {
    __shared__ __align__(16) float sWih[3 * H * H];
    __shared__ __align__(16) float sWhh[3 * H * H];
    __shared__ float sbih[3 * H], sbhh[3 * H], scb[H];

    for (int i = threadIdx.x; i < 3 * H * H; i += blockDim.x) {
        sWih[i] = gWih[i];
        sWhh[i] = gWhh[i];
    }
    for (int i = threadIdx.x; i < 3 * H; i += blockDim.x) {
        sbih[i] = gbih[i];
        sbhh[i] = gbhh[i];
    }
    if (threadIdx.x < H) scb[threadIdx.x] = cb[threadIdx.x];
    __syncthreads();

    int n = blockIdx.x * blockDim.x + threadIdx.x;
    if (n >= NN) return;

    unsigned long long m2[H / 2], h2[H / 2];
    {
        const float4* ag4 = (const float4*)(d_agg + (size_t)n * H);
        const float4* hh4 = (const float4*)(d_h + (size_t)n * H);
#pragma unroll
        for (int q = 0; q < H / 4; q++) {
            float4 a = ag4[q];
            float b0 = fmaxf(a.x + scb[q * 4 + 0], 0.f);
            float b1 = fmaxf(a.y + scb[q * 4 + 1], 0.f);
            float b2 = fmaxf(a.z + scb[q * 4 + 2], 0.f);
            float b3 = fmaxf(a.w + scb[q * 4 + 3], 0.f);
            m2[2 * q + 0] = pk(b0, b1);
            m2[2 * q + 1] = pk(b2, b3);
            float4 hh = hh4[q];
            h2[2 * q + 0] = pk(hh.x, hh.y);
            h2[2 * q + 1] = pk(hh.z, hh.w);
        }
    }

#pragma unroll 1
    for (int o = 0; o < H; o++) {
        const ulonglong2* Wr = (const ulonglong2*)(sWih + o * H);
        const ulonglong2* Wz = (const ulonglong2*)(sWih + (H + o) * H);
        const ulonglong2* Wn = (const ulonglong2*)(sWih + (2 * H + o) * H);
        const ulonglong2* Vr = (const ulonglong2*)(sWhh + o * H);
        const ulonglong2* Vz = (const ulonglong2*)(sWhh + (H + o) * H);
        const ulonglong2* Vn = (const ulonglong2*)(sWhh + (2 * H + o) * H);
        unsigned long long air = 0, aiz = 0, ain = 0, ahr = 0, ahz = 0, ahn = 0;
#pragma unroll
        for (int p = 0; p < H / 4; p++) {
            ulonglong2 w;
            w = Wr[p]; ffma2(air, m2[2 * p], w.x); ffma2(air, m2[2 * p + 1], w.y);
            w = Wz[p]; ffma2(aiz, m2[2 * p], w.x); ffma2(aiz, m2[2 * p + 1], w.y);
            w = Wn[p]; ffma2(ain, m2[2 * p], w.x); ffma2(ain, m2[2 * p + 1], w.y);
            w = Vr[p]; ffma2(ahr, h2[2 * p], w.x); ffma2(ahr, h2[2 * p + 1], w.y);
            w = Vz[p]; ffma2(ahz, h2[2 * p], w.x); ffma2(ahz, h2[2 * p + 1], w.y);
            w = Vn[p]; ffma2(ahn, h2[2 * p], w.x); ffma2(ahn, h2[2 * p + 1], w.y);
        }
        float2 f;
        f = upk(air); float ir = f.x + f.y + sbih[o];
        f = upk(aiz); float iz = f.x + f.y + sbih[H + o];
        f = upk(ain); float in_ = f.x + f.y + sbih[2 * H + o];
        f = upk(ahr); float hr = f.x + f.y + sbhh[o];
        f = upk(ahz); float hz = f.x + f.y + sbhh[H + o];
        f = upk(ahn); float hn = f.x + f.y + sbhh[2 * H + o];

        float r = sigm(ir + hr);
        float z = sigm(iz + hz);
        float nn = tanh_fast(in_ + r * hn);
        float2 hp = upk(h2[o >> 1]);
        float hdo = (o & 1) ? hp.y : hp.x;
        float hnew = (1.0f - z) * nn + z * hdo;
        d_h[(size_t)n * H + o] = hnew;
        if (outp) outp[(size_t)n * H + o] = hnew;
    }
}

// ---------------- launch ----------------
extern "C" void kernel_launch(void* const* d_in, const int* in_sizes, int n_in,
                              void* d_out, int out_size) {
    const int* node_ids = (const int*)d_in[0];
    const int* edge_ids = (const int*)d_in[1];
    const int* src = (const int*)d_in[2];
    const int* dst = (const int*)d_in[3];
    const float* node_emb = (const float*)d_in[4];
    const float* edge_emb = (const float*)d_in[5];
    const float* proj_W = (const float*)d_in[6];
    const float* proj_b = (const float*)d_in[7];
    const float* eW1 = (const float*)d_in[8];
    const float* eb1 = (const float*)d_in[9];
    const float* eW2 = (const float*)d_in[10];
    const float* eb2 = (const float*)d_in[11];
    const float* conv_bias = (const float*)d_in[12];
    const float* gWih = (const float*)d_in[13];
    const float* gWhh = (const float*)d_in[14];
    const float* gbih = (const float*)d_in[15];
    const float* gbhh = (const float*)d_in[16];
    float* out = (float*)d_out;

    // launches 0..4 (so first k_message is launch index 5 for ncu -s 5)
    k_count<<<NBLK, 256>>>(edge_ids);
    k_scatter<<<NBLK, 256>>>(edge_ids, src, dst);
    k_scan_wtab<<<NTE + 1, 1024>>>(edge_emb, eW1, eb1, eW2, eb2);
    k_scatter2<<<NBLK, 256>>>();
    k_init<<<(NN * H + 255) / 256, 256>>>(node_ids, node_emb, proj_W, proj_b);

    for (int s = 0; s < STEPS; s++) {
        k_message<<<MSG_BLOCKS, MSG_TPB>>>();
        k_agg<<<AGG_BLOCKS, AGG_TPB>>>();
        float* op = (s == STEPS - 1) ? out : nullptr;
        k_gru<<<(NN + 255) / 256, 256>>>(gWih, gWhh, gbih, gbhh, conv_bias, op);
    }
}